// round 2
// baseline (speedup 1.0000x reference)
#include <cuda_runtime.h>
#include <cuda_bf16.h>

// Problem:
//  x  : (1, 64, 28, 28)  fp32   -> view as (2 groups o, 32 ch j, 28 n, 28 m)
//  w1 : (128, 9)         fp32
//  w2 : (32, 7, 9)       fp32
//  out: (1, 256, 28, 28) fp32,  channel = o*128 + c, rolled +1 along height.
//
//  t4[o,n,m,i] = sum_{j,k} x[o*32+j, n, m+k-3] * w2[j,k,i]       (zero-pad width)
//  out[o,c,(n+1)%28,m] = sum_i w1[c,i] * t4[o,n,m,i]

#define NTHREADS 256

__global__ __launch_bounds__(NTHREADS)
void fused_unfold_einsum_kernel(const float* __restrict__ x,
                                const float* __restrict__ w1,
                                const float* __restrict__ w2,
                                float* __restrict__ out) {
    // Shared staging (all 16B-aligned bases)
    __shared__ __align__(16) float xs[32][34];     // padded width: mm = m+3 in [0,34)
    __shared__ __align__(16) float w2t[9 * 224];   // k-major per i: [i][k*32 + j]
    __shared__ __align__(16) float w1s[128 * 12];  // [c][i], padded 9->12 for LDS.128
    __shared__ __align__(16) float t4s[28 * 12];   // [m][i], padded 9->12

    const int tid = threadIdx.x;
    const int b   = blockIdx.x;         // 0..55
    const int og  = b / 28;             // group 0/1
    const int n   = b % 28;             // input height row

    // --- Stage w2 k-major transposed: w2[(j*7+k)*9 + i] -> w2t[i*224 + k*32 + j]
    #pragma unroll
    for (int idx = tid; idx < 9 * 224; idx += NTHREADS) {
        const int i = idx / 224;
        const int r = idx - i * 224;    // k*32 + j
        const int k = r >> 5;
        const int j = r & 31;
        w2t[idx] = w2[(j * 7 + k) * 9 + i];
    }
    // --- Stage w1 into padded rows
    #pragma unroll
    for (int idx = tid; idx < 128 * 9; idx += NTHREADS) {
        const int c = idx / 9;
        const int i = idx - c * 9;
        w1s[c * 12 + i] = w1[idx];
    }
    // --- Stage x row slab with zero halo
    #pragma unroll
    for (int idx = tid; idx < 32 * 34; idx += NTHREADS) {
        const int j  = idx / 34;
        const int mm = idx - j * 34;
        const int m  = mm - 3;
        float v = 0.0f;
        if (m >= 0 && m < 28)
            v = x[((og * 32 + j) * 28 + n) * 28 + m];
        xs[j][mm] = v;
    }
    __syncthreads();

    // --- t4: thread = (i, m). Warps ~uniform in i -> w2t LDS.128 broadcast;
    //     xs reads are consecutive-m -> conflict-free scalar LDS.
    if (tid < 252) {
        const int i = tid / 28;
        const int m = tid - i * 28;
        const float* __restrict__ wrow = &w2t[i * 224];

        float acc0 = 0.f, acc1 = 0.f, acc2 = 0.f, acc3 = 0.f;
        float acc4 = 0.f, acc5 = 0.f, acc6 = 0.f, acc7 = 0.f;

        #pragma unroll
        for (int k = 0; k < 7; ++k) {
            const float4* __restrict__ wv =
                reinterpret_cast<const float4*>(wrow + k * 32);  // 128B-aligned
            #pragma unroll
            for (int jq = 0; jq < 8; ++jq) {
                const float4 w4 = wv[jq];
                const int j = jq * 4;
                acc0 = fmaf(xs[j + 0][m + k], w4.x, acc0);
                acc1 = fmaf(xs[j + 1][m + k], w4.y, acc1);
                acc2 = fmaf(xs[j + 2][m + k], w4.z, acc2);
                acc3 = fmaf(xs[j + 3][m + k], w4.w, acc3);
                // rotate accumulator groups across jq for 8-way chains
                { float t = acc0; acc0 = acc4; acc4 = t; }
                { float t = acc1; acc1 = acc5; acc5 = t; }
                { float t = acc2; acc2 = acc6; acc6 = t; }
                { float t = acc3; acc3 = acc7; acc7 = t; }
            }
        }
        const float t4v = ((acc0 + acc1) + (acc2 + acc3)) +
                          ((acc4 + acc5) + (acc6 + acc7));
        t4s[m * 12 + i] = t4v;
    }
    __syncthreads();

    // --- t5 + roll fused into the store index. Vectorized LDS.128 reads.
    const int nout = (n + 1) % 28;      // jnp.roll(y, +1, axis=2)
    #pragma unroll
    for (int it = 0; it < 14; ++it) {
        const int idx = tid + it * NTHREADS;    // 0..3583
        const int c = idx / 28;
        const int m = idx - c * 28;
        const float4* __restrict__ t4v = reinterpret_cast<const float4*>(&t4s[m * 12]);
        const float4* __restrict__ w1v = reinterpret_cast<const float4*>(&w1s[c * 12]);
        const float4 a0 = t4v[0], a1 = t4v[1], a2 = t4v[2];
        const float4 b0 = w1v[0], b1 = w1v[1], b2 = w1v[2];
        float acc = a0.x * b0.x;
        acc = fmaf(a0.y, b0.y, acc);
        acc = fmaf(a0.z, b0.z, acc);
        acc = fmaf(a0.w, b0.w, acc);
        acc = fmaf(a1.x, b1.x, acc);
        acc = fmaf(a1.y, b1.y, acc);
        acc = fmaf(a1.z, b1.z, acc);
        acc = fmaf(a1.w, b1.w, acc);
        acc = fmaf(a2.x, b2.x, acc);    // i=8; .y/.z/.w are padding, unused
        out[((og * 128 + c) * 28 + nout) * 28 + m] = acc;
    }
}

extern "C" void kernel_launch(void* const* d_in, const int* in_sizes, int n_in,
                              void* d_out, int out_size) {
    const float* x  = (const float*)d_in[0];
    const float* w1 = (const float*)d_in[1];
    const float* w2 = (const float*)d_in[2];
    float* out = (float*)d_out;
    (void)in_sizes; (void)n_in; (void)out_size;

    fused_unfold_einsum_kernel<<<56, NTHREADS>>>(x, w1, w2, out);
}